// round 6
// baseline (speedup 1.0000x reference)
#include <cuda_runtime.h>
#include <cuda_fp16.h>
#include <mma.h>
using namespace nvcuda;

#define N_CLI 100000
#define N_AGG 1000
#define NE    1600000
#define D     128
#define NLAY  3

#define MW    1024                 // padded M width (>= N_AGG)
#define KTOT  1152                 // 128 (xc) + 1024 (M)
#define NKC   18                   // KTOT / 64
#define FUSED_SMEM 67584           // 128*132*4 epilogue tile (mainloop needs 35.8KB)

// ---------------- scratch ----------------
__device__ float  g_xa0[N_AGG * D];
__device__ float  g_xa1[N_AGG * D];
__device__ __half g_Y16[N_AGG * D];
__device__ __half g_xc16a[N_CLI * D];
__device__ __half g_xc16b[N_CLI * D];
__device__ __half g_Bcat[KTOT * D];            // [Wr16 ; Y16] (tail rows stay 0)
__device__ __half g_Mx[(size_t)N_CLI * MW];    // dense mean-matrix, zero-init
__device__ float  g_mean_a[N_AGG * D];
__device__ int    g_csr_c2a[NE];
__device__ int    g_off_c2a[N_AGG + 1];
__device__ int    g_cur_c2a[N_AGG];
__device__ int    g_cnt_c2a[N_AGG];
__device__ int    g_cnt_a2c[N_CLI];
__device__ float  g_invc_a[N_AGG];
__device__ float  g_invc_c[N_CLI];

// ---------------- CSR / counts ----------------
__global__ void zero_int_kernel(int* p, int n) {
    int i = blockIdx.x * blockDim.x + threadIdx.x;
    if (i < n) p[i] = 0;
}

__global__ void hist_c2a_kernel(const int* __restrict__ dst, int* __restrict__ cnt) {
    __shared__ int h[N_AGG];
    for (int i = threadIdx.x; i < N_AGG; i += blockDim.x) h[i] = 0;
    __syncthreads();
    for (int e = blockIdx.x * blockDim.x + threadIdx.x; e < NE; e += gridDim.x * blockDim.x)
        atomicAdd(&h[dst[e]], 1);
    __syncthreads();
    for (int i = threadIdx.x; i < N_AGG; i += blockDim.x)
        if (h[i]) atomicAdd(&cnt[i], h[i]);
}

__global__ void hist_a2c_kernel(const int* __restrict__ dst, int* __restrict__ cnt) {
    int e = blockIdx.x * blockDim.x + threadIdx.x;
    if (e < NE) atomicAdd(&cnt[dst[e]], 1);
}

__global__ void invc_kernel(const int* __restrict__ cnt, float* __restrict__ invc, int n) {
    int i = blockIdx.x * blockDim.x + threadIdx.x;
    if (i < n) invc[i] = 1.0f / fmaxf((float)cnt[i], 1.0f);
}

__global__ void scan_init_kernel(const int* __restrict__ cnt, int* __restrict__ off,
                                 int* __restrict__ cur, float* __restrict__ invc, int n) {
    __shared__ int wsum[32];
    __shared__ int carry;
    int tid = threadIdx.x, lane = tid & 31, wid = tid >> 5;
    if (tid == 0) carry = 0;
    __syncthreads();
    for (int base = 0; base < n; base += 1024) {
        int i = base + tid;
        int v = (i < n) ? cnt[i] : 0;
        int x = v;
        #pragma unroll
        for (int o = 1; o < 32; o <<= 1) {
            int t = __shfl_up_sync(0xffffffffu, x, o);
            if (lane >= o) x += t;
        }
        if (lane == 31) wsum[wid] = x;
        __syncthreads();
        if (wid == 0) {
            int s = wsum[lane];
            #pragma unroll
            for (int o = 1; o < 32; o <<= 1) {
                int t = __shfl_up_sync(0xffffffffu, s, o);
                if (lane >= o) s += t;
            }
            wsum[lane] = s;
        }
        __syncthreads();
        int excl = x - v + (wid ? wsum[wid - 1] : 0) + carry;
        if (i < n) {
            off[i] = excl;
            cur[i] = excl;
            invc[i] = 1.0f / fmaxf((float)v, 1.0f);
        }
        __syncthreads();
        if (tid == 0) carry += wsum[31];
        __syncthreads();
    }
    if (threadIdx.x == 0) off[n] = carry;
}

__global__ void scatter_kernel(const int* __restrict__ src, const int* __restrict__ dst,
                               int* __restrict__ cur, int* __restrict__ csr) {
    int e = blockIdx.x * blockDim.x + threadIdx.x;
    if (e < NE) {
        int p = atomicAdd(&cur[dst[e]], 1);
        csr[p] = src[e];
    }
}

// ---------------- dense mean-matrix build ----------------
__global__ void mzero_kernel(const int* __restrict__ src, const int* __restrict__ dst,
                             __half* __restrict__ Mx) {
    int e = blockIdx.x * blockDim.x + threadIdx.x;
    if (e < NE) Mx[(size_t)dst[e] * MW + src[e]] = __ushort_as_half(0);
}

__global__ void madd_kernel(const int* __restrict__ src, const int* __restrict__ dst,
                            const float* __restrict__ invc, __half* __restrict__ Mx) {
    int e = blockIdx.x * blockDim.x + threadIdx.x;
    if (e < NE) {
        int d = dst[e];
        atomicAdd(&Mx[(size_t)d * MW + src[e]], __float2half(invc[d]));
    }
}

// ---------------- fp32 -> fp16 ----------------
__global__ void f2h_kernel(const float* __restrict__ x, __half* __restrict__ y, int n4) {
    int i = blockIdx.x * blockDim.x + threadIdx.x;
    if (i < n4) {
        float4 v = ((const float4*)x)[i];
        __half2 h0 = __floats2half2_rn(v.x, v.y);
        __half2 h1 = __floats2half2_rn(v.z, v.w);
        float2 pk;
        *(__half2*)&pk.x = h0;
        *(__half2*)&pk.y = h1;
        ((float2*)y)[i] = pk;
    }
}

__global__ void copyh2_kernel(const __half* __restrict__ s, __half* __restrict__ d, int n2) {
    int i = blockIdx.x * blockDim.x + threadIdx.x;
    if (i < n2) ((__half2*)d)[i] = ((const __half2*)s)[i];
}

// ---------------- tiny GEMM: Y16 = xa @ Wl ----------------
__global__ void gemm_small_h_kernel(const float* __restrict__ A, const float* __restrict__ W,
                                    __half* __restrict__ C) {
    __shared__ float row[D];
    int r = blockIdx.x, j = threadIdx.x;
    row[j] = A[r * D + j];
    __syncthreads();
    float acc = 0.f;
    #pragma unroll 8
    for (int k = 0; k < D; k++) acc += row[k] * W[k * D + j];
    C[r * D + j] = __float2half(acc);
}

// xa_new = leaky(mean @ Wl + xa @ Wr + b)
__global__ void agg_update_kernel(const float* __restrict__ mean, const float* __restrict__ xa,
                                  const float* __restrict__ Wl, const float* __restrict__ Wr,
                                  const float* __restrict__ b, float* __restrict__ out) {
    __shared__ float rm[D], rx[D];
    int r = blockIdx.x, j = threadIdx.x;
    rm[j] = mean[r * D + j];
    rx[j] = xa[r * D + j];
    __syncthreads();
    float acc = b[j];
    #pragma unroll 4
    for (int k = 0; k < D; k++) acc += rm[k] * Wl[k * D + j] + rx[k] * Wr[k * D + j];
    out[r * D + j] = (acc >= 0.f) ? acc : 0.1f * acc;
}

// ---------------- c2a aggregation from fp16 client features ----------------
__global__ void agg_c2a_h_kernel(const __half* __restrict__ xc16, const int* __restrict__ csr,
                                 const int* __restrict__ off, const float* __restrict__ invc,
                                 float* __restrict__ mean) {
    int a = blockIdx.x, j = threadIdx.x;
    int s = off[a], e = off[a + 1];
    float acc0 = 0.f, acc1 = 0.f, acc2 = 0.f, acc3 = 0.f;
    int i = s;
    for (; i + 4 <= e; i += 4) {
        int i0 = csr[i], i1 = csr[i + 1], i2 = csr[i + 2], i3 = csr[i + 3];
        acc0 += __half2float(xc16[i0 * D + j]);
        acc1 += __half2float(xc16[i1 * D + j]);
        acc2 += __half2float(xc16[i2 * D + j]);
        acc3 += __half2float(xc16[i3 * D + j]);
    }
    for (; i < e; i++) acc0 += __half2float(xc16[csr[i] * D + j]);
    mean[a * D + j] = (acc0 + acc1 + acc2 + acc3) * invc[a];
}

// ---------------- fused GEMM: xc_new = leaky([xc16|M] @ Bcat + b) ----------------
// BM=128, BN=128, BK=64, 8 warps: warp w -> rows (w>>1)*32, cols (w&1)*64
__global__ void __launch_bounds__(256, 2)
fused_gemm_kernel(const __half* __restrict__ xc16, const __half* __restrict__ Mx,
                  const __half* __restrict__ Bcat, const float* __restrict__ bias,
                  __half* __restrict__ xc_out) {
    extern __shared__ __half sm[];
    __half* sA = sm;                 // [128][72]  (row pitch 144B, 16B-aligned)
    __half* sB = sm + 128 * 72;      // [64][136]
    float* tile = (float*)sm;        // [128][132] epilogue alias

    int tid = threadIdx.x;
    int r0 = blockIdx.x * 128;
    int warp = tid >> 5, wm = warp >> 1, wn = warp & 1;

    wmma::fragment<wmma::accumulator, 16, 16, 16, float> acc[2][4];
    #pragma unroll
    for (int i = 0; i < 2; i++)
        #pragma unroll
        for (int j = 0; j < 4; j++) wmma::fill_fragment(acc[i][j], 0.f);

    for (int kc = 0; kc < NKC; kc++) {
        // A chunk: 128 rows x 64 halfs  (1024 float4 / 256 threads = 4 each)
        #pragma unroll
        for (int i = tid; i < 128 * 8; i += 256) {
            int row = i >> 3, c8 = (i & 7) * 8;
            int rc = min(r0 + row, N_CLI - 1);
            float4 v;
            if (kc < 2) v = *(const float4*)(xc16 + (size_t)rc * D + kc * 64 + c8);
            else        v = *(const float4*)(Mx + (size_t)rc * MW + (kc - 2) * 64 + c8);
            *(float4*)(&sA[row * 72 + c8]) = v;
        }
        // B chunk: 64 rows x 128 halfs
        #pragma unroll
        for (int i = tid; i < 64 * 16; i += 256) {
            int row = i >> 4, c8 = (i & 15) * 8;
            *(float4*)(&sB[row * 136 + c8]) =
                *(const float4*)(Bcat + (size_t)(kc * 64 + row) * D + c8);
        }
        __syncthreads();
        #pragma unroll
        for (int k = 0; k < 64; k += 16) {
            wmma::fragment<wmma::matrix_a, 16, 16, 16, __half, wmma::row_major> af[2];
            #pragma unroll
            for (int i = 0; i < 2; i++)
                wmma::load_matrix_sync(af[i], &sA[(wm * 32 + i * 16) * 72 + k], 72);
            #pragma unroll
            for (int j = 0; j < 4; j++) {
                wmma::fragment<wmma::matrix_b, 16, 16, 16, __half, wmma::row_major> bf;
                wmma::load_matrix_sync(bf, &sB[k * 136 + wn * 64 + j * 16], 136);
                #pragma unroll
                for (int i = 0; i < 2; i++)
                    wmma::mma_sync(acc[i][j], af[i], bf, acc[i][j]);
            }
        }
        __syncthreads();
    }

    // epilogue: fragments -> smem tile -> bias + leaky -> fp16
    #pragma unroll
    for (int i = 0; i < 2; i++)
        #pragma unroll
        for (int j = 0; j < 4; j++)
            wmma::store_matrix_sync(&tile[(wm * 32 + i * 16) * 132 + wn * 64 + j * 16],
                                    acc[i][j], 132, wmma::mem_row_major);
    __syncthreads();

    for (int i = tid; i < 128 * 64; i += 256) {   // half2 granularity
        int row = i >> 6, c2 = i & 63;
        int r = r0 + row;
        if (r < N_CLI) {
            float vx = tile[row * 132 + c2 * 2]     + bias[c2 * 2];
            float vy = tile[row * 132 + c2 * 2 + 1] + bias[c2 * 2 + 1];
            vx = (vx >= 0.f) ? vx : 0.1f * vx;
            vy = (vy >= 0.f) ? vy : 0.1f * vy;
            ((__half2*)xc_out)[(size_t)r * 64 + c2] = __floats2half2_rn(vx, vy);
        }
    }
}

// ---------------- final linear from fp16 features ----------------
__global__ void final_h_kernel(const __half* __restrict__ xc16, const float* __restrict__ Wlin,
                               const float* __restrict__ blin, float* __restrict__ out) {
    int warp = (blockIdx.x * blockDim.x + threadIdx.x) >> 5;
    int lane = threadIdx.x & 31;
    if (warp >= N_CLI) return;
    float2 raw = ((const float2*)xc16)[(size_t)warp * 32 + lane];
    __half2 h0 = *(__half2*)&raw.x;
    __half2 h1 = *(__half2*)&raw.y;
    float2 f0 = __half22float2(h0);
    float2 f1 = __half22float2(h1);
    float4 w = ((const float4*)Wlin)[lane];
    float s = f0.x * w.x + f0.y * w.y + f1.x * w.z + f1.y * w.w;
    #pragma unroll
    for (int o = 16; o; o >>= 1) s += __shfl_xor_sync(0xffffffffu, s, o);
    if (lane == 0) out[warp] = s + blin[0];
}

// ---------------- launch ----------------
extern "C" void kernel_launch(void* const* d_in, const int* in_sizes, int n_in,
                              void* d_out, int out_size) {
    (void)in_sizes; (void)n_in; (void)out_size;
    const float* x_clients = (const float*)d_in[0];
    const float* x_agg     = (const float*)d_in[1];
    const int*   c2a_src   = (const int*)d_in[2];
    const int*   c2a_dst   = (const int*)d_in[3];
    const int*   a2c_src   = (const int*)d_in[4];
    const int*   a2c_dst   = (const int*)d_in[5];
    const float* Wl_c2a    = (const float*)d_in[6];
    const float* Wr_c2a    = (const float*)d_in[7];
    const float* b_c2a     = (const float*)d_in[8];
    const float* Wl_a2c    = (const float*)d_in[9];
    const float* Wr_a2c    = (const float*)d_in[10];
    const float* b_a2c     = (const float*)d_in[11];
    const float* W_lin     = (const float*)d_in[12];
    const float* b_lin     = (const float*)d_in[13];
    float* out = (float*)d_out;

    void *p_xa0, *p_xa1, *p_Y16, *p_xc16a, *p_xc16b, *p_Bcat, *p_Mx, *p_mean;
    void *p_csr_c2a, *p_off_c2a, *p_cur_c2a, *p_cnt_c2a, *p_cnt_a2c, *p_invc_a, *p_invc_c;
    cudaGetSymbolAddress(&p_xa0, g_xa0);
    cudaGetSymbolAddress(&p_xa1, g_xa1);
    cudaGetSymbolAddress(&p_Y16, g_Y16);
    cudaGetSymbolAddress(&p_xc16a, g_xc16a);
    cudaGetSymbolAddress(&p_xc16b, g_xc16b);
    cudaGetSymbolAddress(&p_Bcat, g_Bcat);
    cudaGetSymbolAddress(&p_Mx, g_Mx);
    cudaGetSymbolAddress(&p_mean, g_mean_a);
    cudaGetSymbolAddress(&p_csr_c2a, g_csr_c2a);
    cudaGetSymbolAddress(&p_off_c2a, g_off_c2a);
    cudaGetSymbolAddress(&p_cur_c2a, g_cur_c2a);
    cudaGetSymbolAddress(&p_cnt_c2a, g_cnt_c2a);
    cudaGetSymbolAddress(&p_cnt_a2c, g_cnt_a2c);
    cudaGetSymbolAddress(&p_invc_a, g_invc_a);
    cudaGetSymbolAddress(&p_invc_c, g_invc_c);

    cudaFuncSetAttribute(fused_gemm_kernel, cudaFuncAttributeMaxDynamicSharedMemorySize,
                         FUSED_SMEM);

    __half* xc16b_[2] = {(__half*)p_xc16a, (__half*)p_xc16b};
    float* xab[2] = {(float*)p_xa0, (float*)p_xa1};

    int grid_fg = (N_CLI + 127) / 128;
    int grid_e = (NE + 255) / 256;

    // ---- prep ----
    f2h_kernel<<<(N_CLI * 32 + 255) / 256, 256>>>(x_clients, (__half*)p_xc16a, N_CLI * 32);
    gemm_small_h_kernel<<<N_AGG, 128>>>(x_agg, Wl_a2c, (__half*)p_Y16);

    // ---- counts / invc / dense M build ----
    zero_int_kernel<<<(N_AGG + 255) / 256, 256>>>((int*)p_cnt_c2a, N_AGG);
    zero_int_kernel<<<(N_CLI + 255) / 256, 256>>>((int*)p_cnt_a2c, N_CLI);
    hist_c2a_kernel<<<296, 256>>>(c2a_dst, (int*)p_cnt_c2a);
    hist_a2c_kernel<<<grid_e, 256>>>(a2c_dst, (int*)p_cnt_a2c);
    invc_kernel<<<(N_CLI + 255) / 256, 256>>>((const int*)p_cnt_a2c, (float*)p_invc_c, N_CLI);
    mzero_kernel<<<grid_e, 256>>>(a2c_src, a2c_dst, (__half*)p_Mx);
    madd_kernel<<<grid_e, 256>>>(a2c_src, a2c_dst, (const float*)p_invc_c, (__half*)p_Mx);

    // ---- c2a CSR ----
    scan_init_kernel<<<1, 1024>>>((const int*)p_cnt_c2a, (int*)p_off_c2a,
                                  (int*)p_cur_c2a, (float*)p_invc_a, N_AGG);
    scatter_kernel<<<grid_e, 256>>>(c2a_src, c2a_dst, (int*)p_cur_c2a, (int*)p_csr_c2a);

    const float* xa_in = x_agg;
    const __half* xc16_in = (const __half*)p_xc16a;

    for (int l = 0; l < NLAY; l++) {
        const float* WrA = Wr_a2c + l * D * D;
        const float* bA  = b_a2c + l * D;
        __half* xc16_out = xc16b_[(l + 1) & 1];

        // Bcat = [Wr16 ; Y16]
        f2h_kernel<<<(D * D / 4 + 255) / 256, 256>>>(WrA, (__half*)p_Bcat, D * D / 4);
        copyh2_kernel<<<(N_AGG * D / 2 + 255) / 256, 256>>>((const __half*)p_Y16,
                                                            (__half*)p_Bcat + D * D,
                                                            N_AGG * D / 2);
        // combined GEMM: xc_out = leaky([xc|M] @ Bcat + bA)
        fused_gemm_kernel<<<grid_fg, 256, FUSED_SMEM>>>(
            xc16_in, (const __half*)p_Mx, (const __half*)p_Bcat, bA, xc16_out);

        // c2a path (uses pre-update xc16/xa); dead in last layer
        if (l < NLAY - 1) {
            const float* WlC = Wl_c2a + l * D * D;
            const float* WrC = Wr_c2a + l * D * D;
            const float* bC  = b_c2a + l * D;
            agg_c2a_h_kernel<<<N_AGG, 128>>>(xc16_in, (const int*)p_csr_c2a,
                                             (const int*)p_off_c2a, (const float*)p_invc_a,
                                             (float*)p_mean);
            agg_update_kernel<<<N_AGG, 128>>>((const float*)p_mean, xa_in, WlC, WrC, bC,
                                              xab[l & 1]);
            xa_in = xab[l & 1];
            // Y16 for next layer (Bcat already holds this layer's copy)
            gemm_small_h_kernel<<<N_AGG, 128>>>(xa_in, Wl_a2c + (l + 1) * D * D,
                                                (__half*)p_Y16);
        }
        xc16_in = xc16_out;
    }

    final_h_kernel<<<(N_CLI * 32 + 255) / 256, 256>>>(xc16_in, W_lin, b_lin, out);
}

// round 8
// speedup vs baseline: 1.8056x; 1.8056x over previous
#include <cuda_runtime.h>
#include <cuda_fp16.h>
#include <mma.h>
using namespace nvcuda;

#define N_CLI 100000
#define N_AGG 1000
#define NE    1600000
#define D     128
#define NLAY  3

#define GEMM_SMEM ((64 * 136 + 128 * 136) * 2)   // 52224 B

// ---------------- scratch ----------------
__device__ float  g_xa0[N_AGG * D];
__device__ float  g_xa1[N_AGG * D];
__device__ __half g_Y16[N_AGG * D];
__device__ __half g_xc16a[N_CLI * D];
__device__ __half g_xc16b[N_CLI * D];
__device__ __half g_W16[D * D];
__device__ float  g_Z[(N_CLI + 128) * D];
__device__ float  g_mean_a[N_AGG * D];
__device__ int    g_csr_c2a[NE];
__device__ int    g_csr_a2c[NE];
__device__ int    g_off_c2a[N_AGG + 1];
__device__ int    g_off_a2c[N_CLI + 1];
__device__ int    g_cur_c2a[N_AGG];
__device__ int    g_cur_a2c[N_CLI];
__device__ int    g_cnt_c2a[N_AGG];
__device__ int    g_cnt_a2c[N_CLI];
__device__ int    g_part[128];
__device__ float  g_invc_a[N_AGG];
__device__ float  g_invc_c[N_CLI];

// ---------------- CSR construction ----------------
__global__ void zero_int_kernel(int* p, int n) {
    int i = blockIdx.x * blockDim.x + threadIdx.x;
    if (i < n) p[i] = 0;
}

__global__ void hist_c2a_kernel(const int* __restrict__ dst, int* __restrict__ cnt) {
    __shared__ int h[N_AGG];
    for (int i = threadIdx.x; i < N_AGG; i += blockDim.x) h[i] = 0;
    __syncthreads();
    for (int e = blockIdx.x * blockDim.x + threadIdx.x; e < NE; e += gridDim.x * blockDim.x)
        atomicAdd(&h[dst[e]], 1);
    __syncthreads();
    for (int i = threadIdx.x; i < N_AGG; i += blockDim.x)
        if (h[i]) atomicAdd(&cnt[i], h[i]);
}

__global__ void hist_a2c_kernel(const int* __restrict__ dst, int* __restrict__ cnt) {
    int e = blockIdx.x * blockDim.x + threadIdx.x;
    if (e < NE) atomicAdd(&cnt[dst[e]], 1);
}

__global__ void scan_init_kernel(const int* __restrict__ cnt, int* __restrict__ off,
                                 int* __restrict__ cur, float* __restrict__ invc, int n) {
    __shared__ int wsum[32];
    __shared__ int carry;
    int tid = threadIdx.x, lane = tid & 31, wid = tid >> 5;
    if (tid == 0) carry = 0;
    __syncthreads();
    for (int base = 0; base < n; base += 1024) {
        int i = base + tid;
        int v = (i < n) ? cnt[i] : 0;
        int x = v;
        #pragma unroll
        for (int o = 1; o < 32; o <<= 1) {
            int t = __shfl_up_sync(0xffffffffu, x, o);
            if (lane >= o) x += t;
        }
        if (lane == 31) wsum[wid] = x;
        __syncthreads();
        if (wid == 0) {
            int s = wsum[lane];
            #pragma unroll
            for (int o = 1; o < 32; o <<= 1) {
                int t = __shfl_up_sync(0xffffffffu, s, o);
                if (lane >= o) s += t;
            }
            wsum[lane] = s;
        }
        __syncthreads();
        int excl = x - v + (wid ? wsum[wid - 1] : 0) + carry;
        if (i < n) {
            off[i] = excl;
            cur[i] = excl;
            invc[i] = 1.0f / fmaxf((float)v, 1.0f);
        }
        __syncthreads();
        if (tid == 0) carry += wsum[31];
        __syncthreads();
    }
    if (threadIdx.x == 0) off[n] = carry;
}

__global__ void scan_blocks_kernel(const int* __restrict__ cnt, int* __restrict__ off,
                                   int* __restrict__ part, int n) {
    __shared__ int wsum[32];
    int tid = threadIdx.x, lane = tid & 31, wid = tid >> 5;
    int i = blockIdx.x * 1024 + tid;
    int v = (i < n) ? cnt[i] : 0;
    int x = v;
    #pragma unroll
    for (int o = 1; o < 32; o <<= 1) {
        int t = __shfl_up_sync(0xffffffffu, x, o);
        if (lane >= o) x += t;
    }
    if (lane == 31) wsum[wid] = x;
    __syncthreads();
    if (wid == 0) {
        int s = wsum[lane];
        #pragma unroll
        for (int o = 1; o < 32; o <<= 1) {
            int t = __shfl_up_sync(0xffffffffu, s, o);
            if (lane >= o) s += t;
        }
        wsum[lane] = s;
    }
    __syncthreads();
    int excl = x - v + (wid ? wsum[wid - 1] : 0);
    if (i < n) off[i] = excl;
    if (tid == 1023) part[blockIdx.x] = excl + v;
}

__global__ void scan_part_kernel(int* part, int nb) {
    if (threadIdx.x == 0) {
        int acc = 0;
        for (int b = 0; b < nb; b++) {
            int v = part[b];
            part[b] = acc;
            acc += v;
        }
        part[nb] = acc;
    }
}

__global__ void scan_add_kernel(const int* __restrict__ cnt, int* __restrict__ off,
                                const int* __restrict__ part, int* __restrict__ cur,
                                float* __restrict__ invc, int n, int nb) {
    int i = blockIdx.x * blockDim.x + threadIdx.x;
    if (i < n) {
        int o = off[i] + part[i >> 10];
        off[i] = o;
        cur[i] = o;
        invc[i] = 1.0f / fmaxf((float)cnt[i], 1.0f);
    }
    if (i == 0) off[n] = part[nb];
}

__global__ void scatter_kernel(const int* __restrict__ src, const int* __restrict__ dst,
                               int* __restrict__ cur, int* __restrict__ csr) {
    int e = blockIdx.x * blockDim.x + threadIdx.x;
    if (e < NE) {
        int p = atomicAdd(&cur[dst[e]], 1);
        csr[p] = src[e];
    }
}

// ---------------- fp32 -> fp16 ----------------
__global__ void f2h_kernel(const float* __restrict__ x, __half* __restrict__ y, int n4) {
    int i = blockIdx.x * blockDim.x + threadIdx.x;
    if (i < n4) {
        float4 v = ((const float4*)x)[i];
        __half2 h0 = __floats2half2_rn(v.x, v.y);
        __half2 h1 = __floats2half2_rn(v.z, v.w);
        float2 pk;
        *(__half2*)&pk.x = h0;
        *(__half2*)&pk.y = h1;
        ((float2*)y)[i] = pk;
    }
}

// ---------------- tiny GEMM: Y16 = xa @ Wl ----------------
__global__ void gemm_small_h_kernel(const float* __restrict__ A, const float* __restrict__ W,
                                    __half* __restrict__ C) {
    __shared__ float row[D];
    int r = blockIdx.x, j = threadIdx.x;
    row[j] = A[r * D + j];
    __syncthreads();
    float acc = 0.f;
    #pragma unroll 8
    for (int k = 0; k < D; k++) acc += row[k] * W[k * D + j];
    C[r * D + j] = __float2half(acc);
}

// xa_new = leaky(mean @ Wl + xa @ Wr + b)
__global__ void agg_update_kernel(const float* __restrict__ mean, const float* __restrict__ xa,
                                  const float* __restrict__ Wl, const float* __restrict__ Wr,
                                  const float* __restrict__ b, float* __restrict__ out) {
    __shared__ float rm[D], rx[D];
    int r = blockIdx.x, j = threadIdx.x;
    rm[j] = mean[r * D + j];
    rx[j] = xa[r * D + j];
    __syncthreads();
    float acc = b[j];
    #pragma unroll 4
    for (int k = 0; k < D; k++) acc += rm[k] * Wl[k * D + j] + rx[k] * Wr[k * D + j];
    out[r * D + j] = (acc >= 0.f) ? acc : 0.1f * acc;
}

// ---------------- c2a aggregation: 512 thr = 8 edge-groups x 64 half2 lanes ----------------
__global__ void __launch_bounds__(512)
agg_c2a_h_kernel(const __half* __restrict__ xc16, const int* __restrict__ csr,
                 const int* __restrict__ off, const float* __restrict__ invc,
                 float* __restrict__ mean) {
    __shared__ float2 part[512];
    int a = blockIdx.x;
    int t = threadIdx.x;
    int c2 = t & 63;       // half2 column 0..63
    int g = t >> 6;        // edge group 0..7
    int s = off[a], e = off[a + 1];
    const __half2* X2 = (const __half2*)xc16;
    float2 acc = make_float2(0.f, 0.f);
    int i = s + g;
    for (; i + 8 < e; i += 16) {
        int i0 = csr[i];
        int i1 = csr[i + 8];
        float2 f0 = __half22float2(X2[(size_t)i0 * 64 + c2]);
        float2 f1 = __half22float2(X2[(size_t)i1 * 64 + c2]);
        acc.x += f0.x + f1.x;
        acc.y += f0.y + f1.y;
    }
    if (i < e) {
        float2 f0 = __half22float2(X2[(size_t)csr[i] * 64 + c2]);
        acc.x += f0.x;
        acc.y += f0.y;
    }
    part[t] = acc;
    __syncthreads();
    if (g == 0) {
        float2 m = part[c2];
        #pragma unroll
        for (int k = 1; k < 8; k++) {
            float2 p = part[k * 64 + c2];
            m.x += p.x;
            m.y += p.y;
        }
        float ic = invc[a];
        ((float2*)mean)[a * 64 + c2] = make_float2(m.x * ic, m.y * ic);
    }
}

// ---------------- tensor-core GEMM (validated BM=64 variant) ----------------
__global__ void __launch_bounds__(256, 3)
gemm_h_kernel(const __half* __restrict__ A, const __half* __restrict__ W,
              float* __restrict__ Z, int M) {
    extern __shared__ __half sm[];
    __half* sA = sm;                // [64][136]
    __half* sW = sm + 64 * 136;     // [128][136]
    int tid = threadIdx.x;
    int r0 = blockIdx.x * 64;

    for (int i = tid; i < 64 * 16; i += 256) {
        int row = i >> 4, c8 = (i & 15) * 8;
        int rc = min(r0 + row, M - 1);
        *(float4*)(&sA[row * 136 + c8]) = *(const float4*)(A + (size_t)rc * D + c8);
    }
    for (int i = tid; i < 128 * 16; i += 256) {
        int row = i >> 4, c8 = (i & 15) * 8;
        *(float4*)(&sW[row * 136 + c8]) = *(const float4*)(W + row * D + c8);
    }
    __syncthreads();

    int warp = tid >> 5;
    int wm = warp >> 1;
    int wn = warp & 1;

    wmma::fragment<wmma::accumulator, 16, 16, 16, float> acc[4];
    #pragma unroll
    for (int j = 0; j < 4; j++) wmma::fill_fragment(acc[j], 0.f);

    #pragma unroll
    for (int k = 0; k < 128; k += 16) {
        wmma::fragment<wmma::matrix_a, 16, 16, 16, __half, wmma::row_major> af;
        wmma::load_matrix_sync(af, &sA[(wm * 16) * 136 + k], 136);
        #pragma unroll
        for (int j = 0; j < 4; j++) {
            wmma::fragment<wmma::matrix_b, 16, 16, 16, __half, wmma::row_major> bf;
            wmma::load_matrix_sync(bf, &sW[k * 136 + wn * 64 + j * 16], 136);
            wmma::mma_sync(acc[j], af, bf, acc[j]);
        }
    }

    #pragma unroll
    for (int j = 0; j < 4; j++)
        wmma::store_matrix_sync(&Z[(size_t)(r0 + wm * 16) * D + wn * 64 + j * 16],
                                acc[j], D, wmma::mem_row_major);
}

// ---------------- client update (R3 version, untouched) ----------------
template<bool LAST>
__global__ void client_update_h_kernel(const float* __restrict__ Z, const float* __restrict__ bias,
                                       const __half* __restrict__ Y16,
                                       const int* __restrict__ csr, const int* __restrict__ off,
                                       const float* __restrict__ invc,
                                       __half* __restrict__ xc16,
                                       const float* __restrict__ Wlin,
                                       const float* __restrict__ blin,
                                       float* __restrict__ outv) {
    __shared__ float sb[D];
    if (threadIdx.x < D) sb[threadIdx.x] = bias[threadIdx.x];
    __syncthreads();
    int warp = (blockIdx.x * blockDim.x + threadIdx.x) >> 5;
    int lane = threadIdx.x & 31;
    if (warp >= N_CLI) return;
    int s = off[warp], e = off[warp + 1];
    const float2* Y2 = (const float2*)Y16;
    float4 acc = make_float4(0.f, 0.f, 0.f, 0.f);
    for (int base = s; base < e; base += 32) {
        int nv = min(32, e - base);
        int idx = (lane < nv) ? csr[base + lane] : 0;
        for (int t = 0; t < nv; t++) {
            int a = __shfl_sync(0xffffffffu, idx, t);
            float2 raw = Y2[a * 32 + lane];
            __half2 h0 = *(__half2*)&raw.x;
            __half2 h1 = *(__half2*)&raw.y;
            float2 f0 = __half22float2(h0);
            float2 f1 = __half22float2(h1);
            acc.x += f0.x; acc.y += f0.y; acc.z += f1.x; acc.w += f1.y;
        }
    }
    float ic = invc[warp];
    float4 z = ((const float4*)Z)[warp * 32 + lane];
    float4 b4 = *(const float4*)(&sb[lane * 4]);
    float4 v;
    v.x = z.x + b4.x + acc.x * ic;
    v.y = z.y + b4.y + acc.y * ic;
    v.z = z.z + b4.z + acc.z * ic;
    v.w = z.w + b4.w + acc.w * ic;
    v.x = (v.x >= 0.f) ? v.x : 0.1f * v.x;
    v.y = (v.y >= 0.f) ? v.y : 0.1f * v.y;
    v.z = (v.z >= 0.f) ? v.z : 0.1f * v.z;
    v.w = (v.w >= 0.f) ? v.w : 0.1f * v.w;
    if (LAST) {
        float4 w4 = ((const float4*)Wlin)[lane];
        float p = v.x * w4.x + v.y * w4.y + v.z * w4.z + v.w * w4.w;
        #pragma unroll
        for (int o = 16; o; o >>= 1) p += __shfl_xor_sync(0xffffffffu, p, o);
        if (lane == 0) outv[warp] = p + blin[0];
    } else {
        __half2 h0 = __floats2half2_rn(v.x, v.y);
        __half2 h1 = __floats2half2_rn(v.z, v.w);
        float2 pk;
        *(__half2*)&pk.x = h0;
        *(__half2*)&pk.y = h1;
        ((float2*)xc16)[warp * 32 + lane] = pk;
    }
}

// ---------------- launch ----------------
extern "C" void kernel_launch(void* const* d_in, const int* in_sizes, int n_in,
                              void* d_out, int out_size) {
    (void)in_sizes; (void)n_in; (void)out_size;
    const float* x_clients = (const float*)d_in[0];
    const float* x_agg     = (const float*)d_in[1];
    const int*   c2a_src   = (const int*)d_in[2];
    const int*   c2a_dst   = (const int*)d_in[3];
    const int*   a2c_src   = (const int*)d_in[4];
    const int*   a2c_dst   = (const int*)d_in[5];
    const float* Wl_c2a    = (const float*)d_in[6];
    const float* Wr_c2a    = (const float*)d_in[7];
    const float* b_c2a     = (const float*)d_in[8];
    const float* Wl_a2c    = (const float*)d_in[9];
    const float* Wr_a2c    = (const float*)d_in[10];
    const float* b_a2c     = (const float*)d_in[11];
    const float* W_lin     = (const float*)d_in[12];
    const float* b_lin     = (const float*)d_in[13];
    float* out = (float*)d_out;

    void *p_xa0, *p_xa1, *p_Y16, *p_xc16a, *p_xc16b, *p_W16, *p_Z, *p_mean;
    void *p_csr_c2a, *p_csr_a2c, *p_off_c2a, *p_off_a2c;
    void *p_cur_c2a, *p_cur_a2c, *p_cnt_c2a, *p_cnt_a2c, *p_part, *p_invc_a, *p_invc_c;
    cudaGetSymbolAddress(&p_xa0, g_xa0);
    cudaGetSymbolAddress(&p_xa1, g_xa1);
    cudaGetSymbolAddress(&p_Y16, g_Y16);
    cudaGetSymbolAddress(&p_xc16a, g_xc16a);
    cudaGetSymbolAddress(&p_xc16b, g_xc16b);
    cudaGetSymbolAddress(&p_W16, g_W16);
    cudaGetSymbolAddress(&p_Z, g_Z);
    cudaGetSymbolAddress(&p_mean, g_mean_a);
    cudaGetSymbolAddress(&p_csr_c2a, g_csr_c2a);
    cudaGetSymbolAddress(&p_csr_a2c, g_csr_a2c);
    cudaGetSymbolAddress(&p_off_c2a, g_off_c2a);
    cudaGetSymbolAddress(&p_off_a2c, g_off_a2c);
    cudaGetSymbolAddress(&p_cur_c2a, g_cur_c2a);
    cudaGetSymbolAddress(&p_cur_a2c, g_cur_a2c);
    cudaGetSymbolAddress(&p_cnt_c2a, g_cnt_c2a);
    cudaGetSymbolAddress(&p_cnt_a2c, g_cnt_a2c);
    cudaGetSymbolAddress(&p_part, g_part);
    cudaGetSymbolAddress(&p_invc_a, g_invc_a);
    cudaGetSymbolAddress(&p_invc_c, g_invc_c);

    cudaFuncSetAttribute(gemm_h_kernel, cudaFuncAttributeMaxDynamicSharedMemorySize, GEMM_SMEM);

    __half* xc16b_[2] = {(__half*)p_xc16a, (__half*)p_xc16b};
    float* xab[2] = {(float*)p_xa0, (float*)p_xa1};

    int grid_gemm = (N_CLI + 63) / 64;
    int grid_cu = (N_CLI * 32 + 255) / 256;

    // ---- prep for layer 0 (independent of CSR; gemm_h lands at launch index 3) ----
    f2h_kernel<<<(D * D / 4 + 255) / 256, 256>>>(Wr_a2c, (__half*)p_W16, D * D / 4);
    f2h_kernel<<<(N_CLI * 32 + 255) / 256, 256>>>(x_clients, (__half*)p_xc16a, N_CLI * 32);
    gemm_small_h_kernel<<<N_AGG, 128>>>(x_agg, Wl_a2c, (__half*)p_Y16);
    gemm_h_kernel<<<grid_gemm, 256, GEMM_SMEM>>>((const __half*)p_xc16a, (const __half*)p_W16,
                                                 (float*)p_Z, N_CLI);

    // ---- CSR build ----
    zero_int_kernel<<<(N_AGG + 255) / 256, 256>>>((int*)p_cnt_c2a, N_AGG);
    zero_int_kernel<<<(N_CLI + 255) / 256, 256>>>((int*)p_cnt_a2c, N_CLI);
    hist_c2a_kernel<<<296, 256>>>(c2a_dst, (int*)p_cnt_c2a);
    hist_a2c_kernel<<<(NE + 255) / 256, 256>>>(a2c_dst, (int*)p_cnt_a2c);
    scan_init_kernel<<<1, 1024>>>((const int*)p_cnt_c2a, (int*)p_off_c2a,
                                  (int*)p_cur_c2a, (float*)p_invc_a, N_AGG);
    int nb = (N_CLI + 1023) / 1024;
    scan_blocks_kernel<<<nb, 1024>>>((const int*)p_cnt_a2c, (int*)p_off_a2c, (int*)p_part, N_CLI);
    scan_part_kernel<<<1, 32>>>((int*)p_part, nb);
    scan_add_kernel<<<(N_CLI + 255) / 256, 256>>>((const int*)p_cnt_a2c, (int*)p_off_a2c,
                                                  (const int*)p_part, (int*)p_cur_a2c,
                                                  (float*)p_invc_c, N_CLI, nb);
    scatter_kernel<<<(NE + 255) / 256, 256>>>(c2a_src, c2a_dst, (int*)p_cur_c2a, (int*)p_csr_c2a);
    scatter_kernel<<<(NE + 255) / 256, 256>>>(a2c_src, a2c_dst, (int*)p_cur_a2c, (int*)p_csr_a2c);

    const float* xa_in = x_agg;
    const __half* xc16_in = (const __half*)p_xc16a;

    for (int l = 0; l < NLAY; l++) {
        const float* WlA = Wl_a2c + l * D * D;
        const float* WrA = Wr_a2c + l * D * D;
        const float* bA  = b_a2c + l * D;
        const float* WlC = Wl_c2a + l * D * D;
        const float* WrC = Wr_c2a + l * D * D;
        const float* bC  = b_c2a + l * D;
        __half* xc16_out = xc16b_[(l + 1) & 1];

        // c2a path (uses pre-update xc16 and pre-update xa); dead in last layer
        if (l < NLAY - 1) {
            agg_c2a_h_kernel<<<N_AGG, 512>>>(xc16_in, (const int*)p_csr_c2a,
                                             (const int*)p_off_c2a, (const float*)p_invc_a,
                                             (float*)p_mean);
            agg_update_kernel<<<N_AGG, 128>>>((const float*)p_mean, xa_in, WlC, WrC, bC,
                                              xab[l & 1]);
        }

        // a2c path (layer 0's Y16/Z already computed in prep)
        if (l > 0) {
            gemm_small_h_kernel<<<N_AGG, 128>>>(xa_in, WlA, (__half*)p_Y16);
            f2h_kernel<<<(D * D / 4 + 255) / 256, 256>>>(WrA, (__half*)p_W16, D * D / 4);
            gemm_h_kernel<<<grid_gemm, 256, GEMM_SMEM>>>(xc16_in, (const __half*)p_W16,
                                                         (float*)p_Z, N_CLI);
        }
        if (l < NLAY - 1) {
            client_update_h_kernel<false><<<grid_cu, 256>>>(
                (const float*)p_Z, bA, (const __half*)p_Y16, (const int*)p_csr_a2c,
                (const int*)p_off_a2c, (const float*)p_invc_c, xc16_out,
                W_lin, b_lin, out);
        } else {
            client_update_h_kernel<true><<<grid_cu, 256>>>(
                (const float*)p_Z, bA, (const __half*)p_Y16, (const int*)p_csr_a2c,
                (const int*)p_off_a2c, (const float*)p_invc_c, xc16_out,
                W_lin, b_lin, out);
        }

        if (l < NLAY - 1) xa_in = xab[l & 1];
        xc16_in = xc16_out;
    }
}